// round 1
// baseline (speedup 1.0000x reference)
#include <cuda_runtime.h>
#include <math.h>

#define NSEQ   2048
#define BATCH  2
#define MROWS  (NSEQ * BATCH)   // 4096
#define DIMC   768
#define HEADS  12
#define DHEAD  64
#define QKVC   (3 * DIMC)       // 2304

// ---------------- scratch (static device globals; no allocation) ----------------
__device__ float g_qkv[MROWS * QKVC];   // [m][j], j = s*768 + h*64 + d
__device__ float g_att[MROWS * DIMC];   // [m][h*64 + d]

// ---------------- shared GEMM-NT core: C[M,Nd] = A[M,768] @ Bm[Nd,768]^T (+bias) ----
// 64x64 block tile, BK=16, 256 threads, 4x4 micro-tile.
__device__ __forceinline__ void gemm_nt_core(const float* __restrict__ A,
                                             const float* __restrict__ Bm,
                                             const float* __restrict__ bias,
                                             float* __restrict__ C,
                                             int Ndim)
{
    __shared__ float As[16][68];
    __shared__ float Bs[16][68];
    const int K = DIMC;
    const int tid = threadIdx.x;
    const int tm = tid >> 4;        // 0..15
    const int tn = tid & 15;        // 0..15
    const int m0 = blockIdx.y * 64;
    const int n0 = blockIdx.x * 64;
    const int lr = tid >> 2;        // 0..63
    const int lk = (tid & 3) << 2;  // 0,4,8,12

    float acc[4][4] = {};
    const float* Aptr = A  + (long)(m0 + lr) * K + lk;
    const float* Bptr = Bm + (long)(n0 + lr) * K + lk;

    for (int k0 = 0; k0 < K; k0 += 16) {
        float4 av = *(const float4*)(Aptr + k0);
        float4 bv = *(const float4*)(Bptr + k0);
        As[lk + 0][lr] = av.x; As[lk + 1][lr] = av.y;
        As[lk + 2][lr] = av.z; As[lk + 3][lr] = av.w;
        Bs[lk + 0][lr] = bv.x; Bs[lk + 1][lr] = bv.y;
        Bs[lk + 2][lr] = bv.z; Bs[lk + 3][lr] = bv.w;
        __syncthreads();
#pragma unroll
        for (int kk = 0; kk < 16; kk++) {
            float4 a = *(const float4*)(&As[kk][tm << 2]);
            float4 b = *(const float4*)(&Bs[kk][tn << 2]);
            float ar[4] = {a.x, a.y, a.z, a.w};
            float br[4] = {b.x, b.y, b.z, b.w};
#pragma unroll
            for (int i = 0; i < 4; i++)
#pragma unroll
                for (int j = 0; j < 4; j++)
                    acc[i][j] += ar[i] * br[j];
        }
        __syncthreads();
    }

#pragma unroll
    for (int i = 0; i < 4; i++) {
        int row = m0 + (tm << 2) + i;
#pragma unroll
        for (int j = 0; j < 4; j++) {
            int col = n0 + (tn << 2) + j;
            float bv = bias ? bias[col] : 0.0f;
            C[(long)row * Ndim + col] = acc[i][j] + bv;
        }
    }
}

__global__ void __launch_bounds__(256)
gemm_qkv_kernel(const float* __restrict__ x, const float* __restrict__ qkv_w)
{
    gemm_nt_core(x, qkv_w, nullptr, g_qkv, QKVC);
}

__global__ void __launch_bounds__(256)
gemm_proj_kernel(const float* __restrict__ proj_w, const float* __restrict__ proj_b,
                 float* __restrict__ out)
{
    gemm_nt_core(g_att, proj_w, proj_b, out, DIMC);
}

// ---------------- RMSNorm + 3D RoPE on q and k (in place) ----------------
// grid = MROWS blocks, 384 threads = 12 warps; warp h handles head h for q then k.
__global__ void __launch_bounds__(384)
normrope_kernel(const float* __restrict__ pos,
                const float* __restrict__ qn_w, const float* __restrict__ kn_w)
{
    const int m    = blockIdx.x;
    const int w    = threadIdx.x >> 5;   // head
    const int lane = threadIdx.x & 31;

    const float p0 = pos[m * 3 + 0];
    const float p1 = pos[m * 3 + 1];
    const float p2 = pos[m * 3 + 2];

    // per-lane rotation (lanes 0..29 own rope pair `lane`; lanes 30,31 pass-through)
    float c = 1.0f, s = 0.0f;
    if (lane < 30) {
        int   ax  = lane / 10;
        int   fi  = lane - ax * 10;
        float freq = __powf(10000.0f, -(float)fi * 0.1f);
        float pp   = (ax == 0) ? p0 : ((ax == 1) ? p1 : p2);
        float ang  = pp * freq;
        __sincosf(ang, &s, &c);
    }

#pragma unroll
    for (int t = 0; t < 2; t++) {
        float* base = g_qkv + (long)m * QKVC + t * DIMC + w * DHEAD;
        const float* wn = (t == 0) ? qn_w : kn_w;
        float v0 = base[2 * lane];
        float v1 = base[2 * lane + 1];
        float ss = v0 * v0 + v1 * v1;
#pragma unroll
        for (int off = 16; off > 0; off >>= 1)
            ss += __shfl_xor_sync(0xffffffffu, ss, off);
        float inv = rsqrtf(ss * (1.0f / 64.0f) + 1e-6f);
        v0 *= inv * wn[2 * lane];
        v1 *= inv * wn[2 * lane + 1];
        if (lane < 30) {
            float e = v0, o = v1;
            v0 = e * c - o * s;
            v1 = e * s + o * c;
        }
        base[2 * lane]     = v0;
        base[2 * lane + 1] = v1;
    }
}

// ---------------- flash attention (fp32) ----------------
// grid = (NSEQ/64, BATCH*HEADS), 256 threads. Br = Bc = 64.
#define SM_STRIDE 65
#define SM_TILE   (64 * SM_STRIDE)
#define ATTN_SMEM_BYTES ((4 * SM_TILE + 3 * 64) * 4)

__global__ void __launch_bounds__(256)
attn_kernel()
{
    extern __shared__ float sm[];
    float* Qs  = sm;
    float* Ks  = sm + SM_TILE;
    float* Vs  = sm + 2 * SM_TILE;
    float* Ss  = sm + 3 * SM_TILE;
    float* m_s = sm + 4 * SM_TILE;
    float* l_s = m_s + 64;
    float* a_s = l_s + 64;

    const float scale = 0.125f;  // DH^-0.5
    const int tid = threadIdx.x;
    const int bh  = blockIdx.y;
    const int b   = bh / HEADS;
    const int h   = bh - b * HEADS;
    const int q0  = blockIdx.x * 64;

    const float* qbase = g_qkv + (long)(b * NSEQ + q0) * QKVC + h * DHEAD;
    const float* kbase = g_qkv + (long)(b * NSEQ) * QKVC + DIMC     + h * DHEAD;
    const float* vbase = g_qkv + (long)(b * NSEQ) * QKVC + 2 * DIMC + h * DHEAD;

#pragma unroll
    for (int i = 0; i < 16; i++) {
        int idx = tid + i * 256;
        int r = idx >> 6, cidx = idx & 63;
        Qs[r * SM_STRIDE + cidx] = qbase[(long)r * QKVC + cidx];
    }
    if (tid < 64) { m_s[tid] = -1e30f; l_s[tid] = 0.0f; }

    const int tm = tid >> 4;   // 0..15 (rows)
    const int tn = tid & 15;   // 0..15 (cols)
    const int w    = tid >> 5;
    const int lane = tid & 31;

    float o[4][4] = {};

    for (int kb = 0; kb < NSEQ / 64; kb++) {
        __syncthreads();  // prev-iter consumers done (and Q/stat init on iter 0)
#pragma unroll
        for (int i = 0; i < 16; i++) {
            int idx = tid + i * 256;
            int r = idx >> 6, cidx = idx & 63;
            Ks[r * SM_STRIDE + cidx] = kbase[(long)(kb * 64 + r) * QKVC + cidx];
            Vs[r * SM_STRIDE + cidx] = vbase[(long)(kb * 64 + r) * QKVC + cidx];
        }
        __syncthreads();

        // S = (Q @ K^T) * scale
        float acc[4][4] = {};
#pragma unroll 4
        for (int d = 0; d < 64; d++) {
            float a_[4], b_[4];
#pragma unroll
            for (int i = 0; i < 4; i++) a_[i] = Qs[(tm * 4 + i) * SM_STRIDE + d];
#pragma unroll
            for (int j = 0; j < 4; j++) b_[j] = Ks[(tn * 4 + j) * SM_STRIDE + d];
#pragma unroll
            for (int i = 0; i < 4; i++)
#pragma unroll
                for (int j = 0; j < 4; j++)
                    acc[i][j] += a_[i] * b_[j];
        }
#pragma unroll
        for (int i = 0; i < 4; i++)
#pragma unroll
            for (int j = 0; j < 4; j++)
                Ss[(tm * 4 + i) * SM_STRIDE + tn * 4 + j] = acc[i][j] * scale;
        __syncthreads();

        // online softmax: warp w owns rows 8w..8w+7
#pragma unroll
        for (int rr = 0; rr < 8; rr++) {
            int r = w * 8 + rr;
            float x0 = Ss[r * SM_STRIDE + lane];
            float x1 = Ss[r * SM_STRIDE + lane + 32];
            float mx = fmaxf(x0, x1);
#pragma unroll
            for (int off = 16; off > 0; off >>= 1)
                mx = fmaxf(mx, __shfl_xor_sync(0xffffffffu, mx, off));
            float mold = m_s[r];
            float mnew = fmaxf(mold, mx);
            float pe0 = __expf(x0 - mnew);
            float pe1 = __expf(x1 - mnew);
            float ssum = pe0 + pe1;
#pragma unroll
            for (int off = 16; off > 0; off >>= 1)
                ssum += __shfl_xor_sync(0xffffffffu, ssum, off);
            Ss[r * SM_STRIDE + lane]      = pe0;
            Ss[r * SM_STRIDE + lane + 32] = pe1;
            if (lane == 0) {
                float alpha = __expf(mold - mnew);
                a_s[r] = alpha;
                l_s[r] = l_s[r] * alpha + ssum;
                m_s[r] = mnew;
            }
        }
        __syncthreads();

        // O = O*alpha + P @ V
        float al[4];
#pragma unroll
        for (int i = 0; i < 4; i++) al[i] = a_s[tm * 4 + i];
#pragma unroll
        for (int i = 0; i < 4; i++)
#pragma unroll
            for (int j = 0; j < 4; j++)
                o[i][j] *= al[i];
#pragma unroll 4
        for (int d = 0; d < 64; d++) {
            float p_[4], v_[4];
#pragma unroll
            for (int i = 0; i < 4; i++) p_[i] = Ss[(tm * 4 + i) * SM_STRIDE + d];
#pragma unroll
            for (int j = 0; j < 4; j++) v_[j] = Vs[d * SM_STRIDE + tn * 4 + j];
#pragma unroll
            for (int i = 0; i < 4; i++)
#pragma unroll
                for (int j = 0; j < 4; j++)
                    o[i][j] += p_[i] * v_[j];
        }
    }

    float* obase = g_att + (long)(b * NSEQ + q0) * DIMC + h * DHEAD;
#pragma unroll
    for (int i = 0; i < 4; i++) {
        float linv = 1.0f / l_s[tm * 4 + i];
#pragma unroll
        for (int j = 0; j < 4; j++)
            obase[(long)(tm * 4 + i) * DIMC + tn * 4 + j] = o[i][j] * linv;
    }
}

// ---------------- launch ----------------
extern "C" void kernel_launch(void* const* d_in, const int* in_sizes, int n_in,
                              void* d_out, int out_size)
{
    const float* x      = (const float*)d_in[0];
    const float* pos    = (const float*)d_in[1];
    const float* qkv_w  = (const float*)d_in[2];
    const float* proj_w = (const float*)d_in[3];
    const float* proj_b = (const float*)d_in[4];
    const float* qn_w   = (const float*)d_in[5];
    const float* kn_w   = (const float*)d_in[6];
    float* out = (float*)d_out;

    // idempotent; legal outside stream ops during capture
    cudaFuncSetAttribute(attn_kernel,
                         cudaFuncAttributeMaxDynamicSharedMemorySize,
                         ATTN_SMEM_BYTES);

    gemm_qkv_kernel<<<dim3(QKVC / 64, MROWS / 64), 256>>>(x, qkv_w);
    normrope_kernel<<<MROWS, 384>>>(pos, qn_w, kn_w);
    attn_kernel<<<dim3(NSEQ / 64, BATCH * HEADS), 256, ATTN_SMEM_BYTES>>>();
    gemm_proj_kernel<<<dim3(DIMC / 64, MROWS / 64), 256>>>(proj_w, proj_b, out);
}

// round 12
// speedup vs baseline: 2.2772x; 2.2772x over previous
#include <cuda_runtime.h>
#include <cuda_bf16.h>
#include <cstdint>
#include <math.h>

#define NSEQ   2048
#define BATCH  2
#define MROWS  4096
#define DIMC   768
#define HEADS  12
#define DHEAD  64
#define QKVC   2304
#define BH     (BATCH * HEADS)   // 24

// ---------------- scratch (static device globals; no allocation) ----------------
__device__ float g_qkv[MROWS * QKVC];
__device__ float g_att[MROWS * DIMC];
__device__ __nv_bfloat16 g_x_hi[MROWS * DIMC],  g_x_lo[MROWS * DIMC];
__device__ __nv_bfloat16 g_w_hi[QKVC * DIMC],   g_w_lo[QKVC * DIMC];
__device__ __nv_bfloat16 g_pw_hi[DIMC * DIMC],  g_pw_lo[DIMC * DIMC];
__device__ __nv_bfloat16 g_a_hi[MROWS * DIMC],  g_a_lo[MROWS * DIMC];
// head-major [b][h][n][d] bf16 splits for attention (q pre-scaled by 0.125)
__device__ __nv_bfloat16 g_q_hi[BH * NSEQ * DHEAD], g_q_lo[BH * NSEQ * DHEAD];
__device__ __nv_bfloat16 g_k_hi[BH * NSEQ * DHEAD], g_k_lo[BH * NSEQ * DHEAD];
__device__ __nv_bfloat16 g_v_hi[BH * NSEQ * DHEAD], g_v_lo[BH * NSEQ * DHEAD];

// ---------------- mma.sync m16n8k16 bf16 (baseline PTX, works on sm_103) --------
__device__ __forceinline__ void mma_bf16(float* c, const uint32_t* a, const uint32_t* b)
{
    asm volatile(
        "mma.sync.aligned.m16n8k16.row.col.f32.bf16.bf16.f32 "
        "{%0,%1,%2,%3}, {%4,%5,%6,%7}, {%8,%9}, {%0,%1,%2,%3};"
        : "+f"(c[0]), "+f"(c[1]), "+f"(c[2]), "+f"(c[3])
        : "r"(a[0]), "r"(a[1]), "r"(a[2]), "r"(a[3]), "r"(b[0]), "r"(b[1]));
}
__device__ __forceinline__ uint32_t b2u(__nv_bfloat162 h) {
    uint32_t u; memcpy(&u, &h, 4); return u;
}

// ================= hi/lo split kernel =================
__global__ void __launch_bounds__(256)
split_kernel(const float* __restrict__ src, __nv_bfloat16* __restrict__ hi,
             __nv_bfloat16* __restrict__ lo, int n4)
{
    int i = blockIdx.x * 256 + threadIdx.x;
    if (i >= n4) return;
    float4 v = ((const float4*)src)[i];
    float vv[4] = {v.x, v.y, v.z, v.w};
    ushort4 h, l;
    unsigned short* hp = &h.x; unsigned short* lp = &l.x;
#pragma unroll
    for (int j = 0; j < 4; j++) {
        __nv_bfloat16 hb = __float2bfloat16(vv[j]);
        float r = vv[j] - __bfloat162float(hb);
        hp[j] = __bfloat16_as_ushort(hb);
        lp[j] = __bfloat16_as_ushort(__float2bfloat16(r));
    }
    ((ushort4*)hi)[i] = h;
    ((ushort4*)lo)[i] = l;
}

// ================= mma GEMM: C[M,Nd] = A[M,768] @ B[Nd,768]^T (+bias) ============
// 128x128 block tile, k-chunk 32, 8 warps (warp tile 32x64), double-buffered smem.
#define GK    32
#define GSTR  40                       // smem row stride (elems): conflict-free
#define GTILE (128 * GSTR)
#define GBUFE (4 * GTILE)
#define GEMM_SMEM (2 * GBUFE * 2)      // 81920 bytes

__global__ void __launch_bounds__(256)
tc_gemm(const __nv_bfloat16* __restrict__ Ah, const __nv_bfloat16* __restrict__ Al,
        const __nv_bfloat16* __restrict__ Bh, const __nv_bfloat16* __restrict__ Bl,
        const float* __restrict__ bias, float* __restrict__ C, int Nd)
{
    extern __shared__ __nv_bfloat16 sm[];
    const int tid = threadIdx.x, wid = tid >> 5, lane = tid & 31;
    const int m0 = blockIdx.y << 7, n0 = blockIdx.x << 7;
    const int wm = wid & 3, wn = wid >> 2;
    const int lr = lane >> 2, lc = (lane & 3) << 1;

    float acc[2][8][4] = {};
    const __nv_bfloat16* gsrc[4] = {Ah, Al, Bh, Bl};
    uint4 pf[8];

    // prologue: chunk 0 straight to smem
#pragma unroll
    for (int i = 0; i < 8; i++) {
        int v = i * 256 + tid;
        int t = v >> 9, r = (v >> 2) & 127, c4 = v & 3;
        int grow = (t < 2 ? m0 : n0) + r;
        uint4 d = *(const uint4*)(gsrc[t] + (size_t)grow * DIMC + c4 * 8);
        *(uint4*)(sm + t * GTILE + r * GSTR + c4 * 8) = d;
    }
    __syncthreads();

    for (int c = 0; c < 24; c++) {
        if (c + 1 < 24) {
            const int k0 = (c + 1) * GK;
#pragma unroll
            for (int i = 0; i < 8; i++) {
                int v = i * 256 + tid;
                int t = v >> 9, r = (v >> 2) & 127, c4 = v & 3;
                int grow = (t < 2 ? m0 : n0) + r;
                pf[i] = *(const uint4*)(gsrc[t] + (size_t)grow * DIMC + k0 + c4 * 8);
            }
        }
        const __nv_bfloat16* buf = sm + (c & 1) * GBUFE;
        const __nv_bfloat16* sAh = buf;
        const __nv_bfloat16* sAl = buf + GTILE;
        const __nv_bfloat16* sBh = buf + 2 * GTILE;
        const __nv_bfloat16* sBl = buf + 3 * GTILE;
#pragma unroll
        for (int kf = 0; kf < 2; kf++) {
            const int ko = kf * 16;
            uint32_t ah[2][4], al[2][4];
#pragma unroll
            for (int mt = 0; mt < 2; mt++) {
                const int r = wm * 32 + mt * 16 + lr;
                ah[mt][0] = *(const uint32_t*)(sAh + r * GSTR + ko + lc);
                ah[mt][1] = *(const uint32_t*)(sAh + (r + 8) * GSTR + ko + lc);
                ah[mt][2] = *(const uint32_t*)(sAh + r * GSTR + ko + lc + 8);
                ah[mt][3] = *(const uint32_t*)(sAh + (r + 8) * GSTR + ko + lc + 8);
                al[mt][0] = *(const uint32_t*)(sAl + r * GSTR + ko + lc);
                al[mt][1] = *(const uint32_t*)(sAl + (r + 8) * GSTR + ko + lc);
                al[mt][2] = *(const uint32_t*)(sAl + r * GSTR + ko + lc + 8);
                al[mt][3] = *(const uint32_t*)(sAl + (r + 8) * GSTR + ko + lc + 8);
            }
#pragma unroll
            for (int nt = 0; nt < 8; nt++) {
                const int rn = wn * 64 + nt * 8 + lr;
                uint32_t bh2[2], bl2[2];
                bh2[0] = *(const uint32_t*)(sBh + rn * GSTR + ko + lc);
                bh2[1] = *(const uint32_t*)(sBh + rn * GSTR + ko + lc + 8);
                bl2[0] = *(const uint32_t*)(sBl + rn * GSTR + ko + lc);
                bl2[1] = *(const uint32_t*)(sBl + rn * GSTR + ko + lc + 8);
#pragma unroll
                for (int mt = 0; mt < 2; mt++) {
                    mma_bf16(acc[mt][nt], ah[mt], bh2);
                    mma_bf16(acc[mt][nt], ah[mt], bl2);
                    mma_bf16(acc[mt][nt], al[mt], bh2);
                }
            }
        }
        if (c + 1 < 24) {
            __nv_bfloat16* nbuf = sm + ((c + 1) & 1) * GBUFE;
#pragma unroll
            for (int i = 0; i < 8; i++) {
                int v = i * 256 + tid;
                int t = v >> 9, r = (v >> 2) & 127, c4 = v & 3;
                *(uint4*)(nbuf + t * GTILE + r * GSTR + c4 * 8) = pf[i];
            }
        }
        __syncthreads();
    }
#pragma unroll
    for (int mt = 0; mt < 2; mt++)
#pragma unroll
        for (int nt = 0; nt < 8; nt++) {
            const int r0 = m0 + wm * 32 + mt * 16 + lr;
            const int cc = n0 + wn * 64 + nt * 8 + lc;
            float b0 = bias ? bias[cc] : 0.0f, b1 = bias ? bias[cc + 1] : 0.0f;
            float2 v0 = {acc[mt][nt][0] + b0, acc[mt][nt][1] + b1};
            float2 v1 = {acc[mt][nt][2] + b0, acc[mt][nt][3] + b1};
            *(float2*)(C + (size_t)r0 * Nd + cc)       = v0;
            *(float2*)(C + (size_t)(r0 + 8) * Nd + cc) = v1;
        }
}

// ---------------- RMSNorm + 3D RoPE -> bf16 hi/lo head-major Q/K/V ---------------
__global__ void __launch_bounds__(384)
normrope_kernel(const float* __restrict__ pos,
                const float* __restrict__ qn_w, const float* __restrict__ kn_w)
{
    const int m    = blockIdx.x;
    const int h    = threadIdx.x >> 5;
    const int lane = threadIdx.x & 31;
    const int b    = m >> 11, n = m & (NSEQ - 1);

    const float p0 = pos[m * 3 + 0];
    const float p1 = pos[m * 3 + 1];
    const float p2 = pos[m * 3 + 2];

    float c = 1.0f, s = 0.0f;
    if (lane < 30) {
        int   ax  = lane / 10;
        int   fi  = lane - ax * 10;
        float freq = __powf(10000.0f, -(float)fi * 0.1f);
        float pp   = (ax == 0) ? p0 : ((ax == 1) ? p1 : p2);
        __sincosf(pp * freq, &s, &c);
    }

    const size_t obase = ((size_t)(b * HEADS + h) * NSEQ + n) * DHEAD + 2 * lane;
    const float* qkvrow = g_qkv + (size_t)m * QKVC + h * DHEAD;

#pragma unroll
    for (int t = 0; t < 2; t++) {
        const float* base = qkvrow + t * DIMC;
        const float* wn = (t == 0) ? qn_w : kn_w;
        float v0 = base[2 * lane], v1 = base[2 * lane + 1];
        float ss = v0 * v0 + v1 * v1;
#pragma unroll
        for (int off = 16; off > 0; off >>= 1)
            ss += __shfl_xor_sync(0xffffffffu, ss, off);
        float inv = rsqrtf(ss * (1.0f / 64.0f) + 1e-6f);
        v0 *= inv * wn[2 * lane];
        v1 *= inv * wn[2 * lane + 1];
        if (lane < 30) {
            float e = v0, o = v1;
            v0 = e * c - o * s;
            v1 = e * s + o * c;
        }
        if (t == 0) { v0 *= 0.125f; v1 *= 0.125f; }   // fold softmax scale into q
        __nv_bfloat162 hi = __floats2bfloat162_rn(v0, v1);
        __nv_bfloat162 lo = __floats2bfloat162_rn(v0 - __bfloat162float(hi.x),
                                                  v1 - __bfloat162float(hi.y));
        __nv_bfloat16* dh = (t == 0) ? g_q_hi : g_k_hi;
        __nv_bfloat16* dl = (t == 0) ? g_q_lo : g_k_lo;
        *(uint32_t*)(dh + obase) = b2u(hi);
        *(uint32_t*)(dl + obase) = b2u(lo);
    }
    {   // v: split only
        const float* base = qkvrow + 2 * DIMC;
        float v0 = base[2 * lane], v1 = base[2 * lane + 1];
        __nv_bfloat162 hi = __floats2bfloat162_rn(v0, v1);
        __nv_bfloat162 lo = __floats2bfloat162_rn(v0 - __bfloat162float(hi.x),
                                                  v1 - __bfloat162float(hi.y));
        *(uint32_t*)(g_v_hi + obase) = b2u(hi);
        *(uint32_t*)(g_v_lo + obase) = b2u(lo);
    }
}

// ---------------- flash attention via mma.sync (FA2 register layout) -------------
// block: 64 q rows, 4 warps (16 q rows each), kv tile 64, full head dim 64.
#define AST   72
#define ATILE (64 * AST)
#define ATTN_SMEM (6 * ATILE * 2)   // 55296 bytes

__global__ void __launch_bounds__(128)
attn_mma()
{
    extern __shared__ __nv_bfloat16 as_[];
    __nv_bfloat16* Qh = as_;
    __nv_bfloat16* Ql = as_ + ATILE;
    __nv_bfloat16* Kh = as_ + 2 * ATILE;
    __nv_bfloat16* Kl = as_ + 3 * ATILE;
    __nv_bfloat16* Vh = as_ + 4 * ATILE;   // transposed: [d][kv]
    __nv_bfloat16* Vl = as_ + 5 * ATILE;

    const int tid = threadIdx.x, wid = tid >> 5, lane = tid & 31;
    const int lr = lane >> 2, lc = (lane & 3) << 1;
    const int bh = blockIdx.y, q0 = blockIdx.x << 6;
    const size_t hbase = (size_t)bh * NSEQ * DHEAD;

    const __nv_bfloat16* qh0 = g_q_hi + hbase + (size_t)q0 * DHEAD;
    const __nv_bfloat16* ql0 = g_q_lo + hbase + (size_t)q0 * DHEAD;
    const __nv_bfloat16* kh0 = g_k_hi + hbase;
    const __nv_bfloat16* kl0 = g_k_lo + hbase;
    const __nv_bfloat16* vh0 = g_v_hi + hbase;
    const __nv_bfloat16* vl0 = g_v_lo + hbase;

#pragma unroll
    for (int i = 0; i < 4; i++) {
        int v = i * 128 + tid, r = v >> 3, cc = v & 7;
        *(uint4*)(Qh + r * AST + cc * 8) = *(const uint4*)(qh0 + r * 64 + cc * 8);
        *(uint4*)(Ql + r * AST + cc * 8) = *(const uint4*)(ql0 + r * 64 + cc * 8);
    }

    float O[8][4] = {};
    float mst0 = -1e30f, mst1 = -1e30f, lst0 = 0.0f, lst1 = 0.0f;
    const int wr = wid * 16;

    for (int kt = 0; kt < 32; kt++) {
        __syncthreads();
        const size_t kb = (size_t)(kt * 64) * DHEAD;
#pragma unroll
        for (int i = 0; i < 4; i++) {
            int v = i * 128 + tid, r = v >> 3, cc = v & 7;
            *(uint4*)(Kh + r * AST + cc * 8) = *(const uint4*)(kh0 + kb + r * 64 + cc * 8);
            *(uint4*)(Kl + r * AST + cc * 8) = *(const uint4*)(kl0 + kb + r * 64 + cc * 8);
            uint4 vv = *(const uint4*)(vh0 + kb + r * 64 + cc * 8);
            const __nv_bfloat16* e = (const __nv_bfloat16*)&vv;
#pragma unroll
            for (int j = 0; j < 8; j++) Vh[(cc * 8 + j) * AST + r] = e[j];
            uint4 vw = *(const uint4*)(vl0 + kb + r * 64 + cc * 8);
            const __nv_bfloat16* e2 = (const __nv_bfloat16*)&vw;
#pragma unroll
            for (int j = 0; j < 8; j++) Vl[(cc * 8 + j) * AST + r] = e2[j];
        }
        __syncthreads();

        // S = Q K^T (3-way split)
        float S[8][4] = {};
#pragma unroll
        for (int kf = 0; kf < 4; kf++) {
            const int ko = kf * 16;
            const int r = wr + lr;
            uint32_t aqh[4], aql[4];
            aqh[0] = *(const uint32_t*)(Qh + r * AST + ko + lc);
            aqh[1] = *(const uint32_t*)(Qh + (r + 8) * AST + ko + lc);
            aqh[2] = *(const uint32_t*)(Qh + r * AST + ko + lc + 8);
            aqh[3] = *(const uint32_t*)(Qh + (r + 8) * AST + ko + lc + 8);
            aql[0] = *(const uint32_t*)(Ql + r * AST + ko + lc);
            aql[1] = *(const uint32_t*)(Ql + (r + 8) * AST + ko + lc);
            aql[2] = *(const uint32_t*)(Ql + r * AST + ko + lc + 8);
            aql[3] = *(const uint32_t*)(Ql + (r + 8) * AST + ko + lc + 8);
#pragma unroll
            for (int nt = 0; nt < 8; nt++) {
                const int rn = nt * 8 + lr;
                uint32_t bh2[2], bl2[2];
                bh2[0] = *(const uint32_t*)(Kh + rn * AST + ko + lc);
                bh2[1] = *(const uint32_t*)(Kh + rn * AST + ko + lc + 8);
                bl2[0] = *(const uint32_t*)(Kl + rn * AST + ko + lc);
                bl2[1] = *(const uint32_t*)(Kl + rn * AST + ko + lc + 8);
                mma_bf16(S[nt], aqh, bh2);
                mma_bf16(S[nt], aqh, bl2);
                mma_bf16(S[nt], aql, bh2);
            }
        }

        // online softmax (rows r0 = wr+lr, r1 = r0+8)
        float mx0 = -1e30f, mx1 = -1e30f;
#pragma unroll
        for (int nt = 0; nt < 8; nt++) {
            mx0 = fmaxf(mx0, fmaxf(S[nt][0], S[nt][1]));
            mx1 = fmaxf(mx1, fmaxf(S[nt][2], S[nt][3]));
        }
        mx0 = fmaxf(mx0, __shfl_xor_sync(0xffffffffu, mx0, 1));
        mx0 = fmaxf(mx0, __shfl_xor_sync(0xffffffffu, mx0, 2));
        mx1 = fmaxf(mx1, __shfl_xor_sync(0xffffffffu, mx1, 1));
        mx1 = fmaxf(mx1, __shfl_xor_sync(0xffffffffu, mx1, 2));
        const float mn0 = fmaxf(mst0, mx0), mn1 = fmaxf(mst1, mx1);
        const float a0 = __expf(mst0 - mn0), a1 = __expf(mst1 - mn1);
        mst0 = mn0; mst1 = mn1;

        uint32_t ph[8][2], pl[8][2];
        float s0 = 0.0f, s1 = 0.0f;
#pragma unroll
        for (int nt = 0; nt < 8; nt++) {
            float p0 = __expf(S[nt][0] - mn0), p1 = __expf(S[nt][1] - mn0);
            float p2 = __expf(S[nt][2] - mn1), p3 = __expf(S[nt][3] - mn1);
            s0 += p0 + p1; s1 += p2 + p3;
            __nv_bfloat162 h01 = __floats2bfloat162_rn(p0, p1);
            __nv_bfloat162 h23 = __floats2bfloat162_rn(p2, p3);
            __nv_bfloat162 l01 = __floats2bfloat162_rn(p0 - __bfloat162float(h01.x),
                                                       p1 - __bfloat162float(h01.y));
            __nv_bfloat162 l23 = __floats2bfloat162_rn(p2 - __bfloat162float(h23.x),
                                                       p3 - __bfloat162float(h23.y));
            ph[nt][0] = b2u(h01); ph[nt][1] = b2u(h23);
            pl[nt][0] = b2u(l01); pl[nt][1] = b2u(l23);
        }
        s0 += __shfl_xor_sync(0xffffffffu, s0, 1);
        s0 += __shfl_xor_sync(0xffffffffu, s0, 2);
        s1 += __shfl_xor_sync(0xffffffffu, s1, 1);
        s1 += __shfl_xor_sync(0xffffffffu, s1, 2);
        lst0 = lst0 * a0 + s0;
        lst1 = lst1 * a1 + s1;
#pragma unroll
        for (int nt = 0; nt < 8; nt++) {
            O[nt][0] *= a0; O[nt][1] *= a0; O[nt][2] *= a1; O[nt][3] *= a1;
        }

        // O += P V (3-way split); A-fragments come straight from S accumulators
#pragma unroll
        for (int t = 0; t < 4; t++) {
            uint32_t aph[4] = {ph[2 * t][0], ph[2 * t][1], ph[2 * t + 1][0], ph[2 * t + 1][1]};
            uint32_t apl[4] = {pl[2 * t][0], pl[2 * t][1], pl[2 * t + 1][0], pl[2 * t + 1][1]};
            const int ko = t * 16;
#pragma unroll
            for (int nt = 0; nt < 8; nt++) {
                const int rn = nt * 8 + lr;
                uint32_t bvh[2], bvl[2];
                bvh[0] = *(const uint32_t*)(Vh + rn * AST + ko + lc);
                bvh[1] = *(const uint32_t*)(Vh + rn * AST + ko + lc + 8);
                bvl[0] = *(const uint32_t*)(Vl + rn * AST + ko + lc);
                bvl[1] = *(const uint32_t*)(Vl + rn * AST + ko + lc + 8);
                mma_bf16(O[nt], aph, bvh);
                mma_bf16(O[nt], aph, bvl);
                mma_bf16(O[nt], apl, bvh);
            }
        }
    }

    const int b = bh / HEADS, h = bh % HEADS;
    const float li0 = 1.0f / lst0, li1 = 1.0f / lst1;
    const int r0 = q0 + wr + lr;
#pragma unroll
    for (int nt = 0; nt < 8; nt++) {
        const int cc = h * 64 + nt * 8 + lc;
        float2 v0 = {O[nt][0] * li0, O[nt][1] * li0};
        float2 v1 = {O[nt][2] * li1, O[nt][3] * li1};
        *(float2*)(g_att + (size_t)(b * NSEQ + r0) * DIMC + cc)       = v0;
        *(float2*)(g_att + (size_t)(b * NSEQ + r0 + 8) * DIMC + cc)   = v1;
    }
}

// ---------------- launch ----------------
extern "C" void kernel_launch(void* const* d_in, const int* in_sizes, int n_in,
                              void* d_out, int out_size)
{
    const float* x      = (const float*)d_in[0];
    const float* pos    = (const float*)d_in[1];
    const float* qkv_w  = (const float*)d_in[2];
    const float* proj_w = (const float*)d_in[3];
    const float* proj_b = (const float*)d_in[4];
    const float* qn_w   = (const float*)d_in[5];
    const float* kn_w   = (const float*)d_in[6];
    float* out = (float*)d_out;

    cudaFuncSetAttribute(tc_gemm,
                         cudaFuncAttributeMaxDynamicSharedMemorySize, GEMM_SMEM);
    cudaFuncSetAttribute(attn_mma,
                         cudaFuncAttributeMaxDynamicSharedMemorySize, ATTN_SMEM);

    __nv_bfloat16 *xh, *xl, *wh, *wl, *pwh, *pwl, *ah, *al;
    cudaGetSymbolAddress((void**)&xh,  g_x_hi);  cudaGetSymbolAddress((void**)&xl,  g_x_lo);
    cudaGetSymbolAddress((void**)&wh,  g_w_hi);  cudaGetSymbolAddress((void**)&wl,  g_w_lo);
    cudaGetSymbolAddress((void**)&pwh, g_pw_hi); cudaGetSymbolAddress((void**)&pwl, g_pw_lo);
    cudaGetSymbolAddress((void**)&ah,  g_a_hi);  cudaGetSymbolAddress((void**)&al,  g_a_lo);
    float *qkv, *att;
    cudaGetSymbolAddress((void**)&qkv, g_qkv);
    cudaGetSymbolAddress((void**)&att, g_att);

    const int nx = MROWS * DIMC / 4, nw = QKVC * DIMC / 4, np = DIMC * DIMC / 4;
    split_kernel<<<(nx + 255) / 256, 256>>>(x, xh, xl, nx);
    split_kernel<<<(nw + 255) / 256, 256>>>(qkv_w, wh, wl, nw);
    split_kernel<<<(np + 255) / 256, 256>>>(proj_w, pwh, pwl, np);

    tc_gemm<<<dim3(QKVC / 128, MROWS / 128), 256, GEMM_SMEM>>>(
        xh, xl, wh, wl, nullptr, qkv, QKVC);

    normrope_kernel<<<MROWS, 384>>>(pos, qn_w, kn_w);

    attn_mma<<<dim3(NSEQ / 64, BH), 128, ATTN_SMEM>>>();

    split_kernel<<<(nx + 255) / 256, 256>>>(att, ah, al, nx);
    tc_gemm<<<dim3(DIMC / 128, MROWS / 128), 256, GEMM_SMEM>>>(
        ah, al, pwh, pwl, proj_b, out, DIMC);
}